// round 7
// baseline (speedup 1.0000x reference)
#include <cuda_runtime.h>

// Single fused kernel. Block layout: g = bid & 7; warps 0..7 handle
// b = (bid>>3)*8 + warp. Each block gathers its group's 4096 weights
// directly from the [L, G] tensor into smem (stride-8 scalar loads,
// L2-resident), then runs the proven 32x{LDG.128 + LDS.128} dot loop.
__global__ __launch_bounds__(256) void grouped_fc_kernel(
    const float* __restrict__ x,
    const float* __restrict__ weight,   // [4096, 8]
    const float* __restrict__ bias,
    float* __restrict__ out)
{
    __shared__ float w_sh[4096];  // 16 KB

    const int g      = blockIdx.x & 7;
    const int b_base = (blockIdx.x >> 3) << 3;

    // Gather weight column g: w_sh[l] = weight[l*8 + g].
    // 4096 / 256 threads = 16 scalar loads per thread (stride-8 in gmem,
    // contiguous in smem). Weight is 128 KB -> L2-resident after 1st touch.
    #pragma unroll
    for (int i = 0; i < 16; i++) {
        int l = threadIdx.x + i * 256;
        w_sh[l] = weight[l * 8 + g];
    }
    __syncthreads();

    const int warp = threadIdx.x >> 5;  // 0..7
    const int lane = threadIdx.x & 31;
    const int row  = (b_base + warp) * 8 + g;

    const float4* __restrict__ xp =
        reinterpret_cast<const float4*>(x + (size_t)row * 4096) + lane;
    const float4* __restrict__ wp =
        reinterpret_cast<const float4*>(w_sh) + lane;

    float a0 = 0.f, a1 = 0.f, a2 = 0.f, a3 = 0.f;

    // 4096 elems / (32 lanes * 4 per float4) = 32 iterations.
    #pragma unroll 8
    for (int i = 0; i < 32; i++) {
        float4 xv = xp[i * 32];
        float4 wv = wp[i * 32];   // conflict-free LDS.128
        a0 = fmaf(xv.x, wv.x, a0);
        a1 = fmaf(xv.y, wv.y, a1);
        a2 = fmaf(xv.z, wv.z, a2);
        a3 = fmaf(xv.w, wv.w, a3);
    }

    float s = (a0 + a1) + (a2 + a3);
    #pragma unroll
    for (int off = 16; off > 0; off >>= 1)
        s += __shfl_xor_sync(0xFFFFFFFFu, s, off);

    if (lane == 0)
        out[row] = s + __ldg(&bias[g]);
}

extern "C" void kernel_launch(void* const* d_in, const int* in_sizes, int n_in,
                              void* d_out, int out_size) {
    const float* x      = (const float*)d_in[0]; // [8192, 8, 4096]
    const float* weight = (const float*)d_in[1]; // [1, 4096, 8]
    const float* bias   = (const float*)d_in[2]; // [8]
    float* out          = (float*)d_out;         // [8192, 8]

    // 8192 blocks: 1024 b-tiles x 8 groups; 8 warps per block.
    grouped_fc_kernel<<<8192, 256>>>(x, weight, bias, out);
}